// round 10
// baseline (speedup 1.0000x reference)
#include <cuda_runtime.h>
#include <cuda_bf16.h>
#include <cuda_fp16.h>
#include <cstdint>
#include <mma.h>
using namespace nvcuda;

// Problem constants (fixed by the reference)
#define NN 20000
#define EE 320000
#define ET (NN + EE)          // edges incl. self loops = 340000
#define HEADS 8
#define MP 20096              // NN padded to multiple of 128 for tensor GEMM
#define NBLK ((NN + 255) / 256)   // 79 blocks for CSR scan

// ---------------- scratch (device globals: no allocation allowed) ----------
__device__ float g_feat[(size_t)MP * 1024];   // transformed features (fp32)
__device__ __half g_feath[(size_t)MP * 1024]; // fp16 shadow for gathers
__device__ float g_accb[(size_t)NN * 256];    // aggregation output
__device__ float g_act0[(size_t)NN * 256];    // activation after layer 0
__device__ float g_act1[(size_t)NN * 256];    // activation after layer 1
__device__ float g_resb[(size_t)MP * 256];    // residual projection
__device__ float g_als[NN * HEADS];
__device__ float g_ald[NN * HEADS];
__device__ int g_src[ET];
__device__ int g_dst[ET];
__device__ int g_is64;
// CSR (dst-sorted adjacency)
__device__ int g_deg[NN];
__device__ int g_off[NN + 1];
__device__ int g_cur[NN];
__device__ int g_csr_src[ET];
__device__ int g_bsum[NBLK];
__device__ int g_boff[NBLK];

// bf16 split buffers. A: activations (MP x 256 max). B: ALL weights, segmented:
//   W0 @ 0 (16384), rW0 @ 16384 (16384), W1 @ 32768 (65536),
//   W2 @ 98304 (262144), rW2 @ 360448 (32768)  -> total 393216 elems
__device__ __nv_bfloat16 g_Ah[(size_t)MP * 256];
__device__ __nv_bfloat16 g_Al[(size_t)MP * 256];
__device__ __nv_bfloat16 g_Bh[393216];
__device__ __nv_bfloat16 g_Bl[393216];

// ---------------- cp.async helpers -----------------------------------------
__device__ __forceinline__ void cp16(unsigned dst, const void* src) {
    asm volatile("cp.async.ca.shared.global [%0], [%1], 16;\n" :: "r"(dst), "l"(src));
}
__device__ __forceinline__ void cp_commit() {
    asm volatile("cp.async.commit_group;\n");
}
template <int N_>
__device__ __forceinline__ void cp_wait() {
    asm volatile("cp.async.wait_group %0;\n" :: "n"(N_));
}

// ---------------- dtype detection: int64 vs int32 edge_index ---------------
__global__ void detect_kernel(const int* __restrict__ raw) {
    __shared__ int any;
    if (threadIdx.x == 0) any = 0;
    __syncthreads();
    for (int i = threadIdx.x; i < 2048; i += blockDim.x)
        if (raw[2 * i + 1] != 0) any = 1;
    __syncthreads();
    if (threadIdx.x == 0) g_is64 = (any == 0);
}

// ---------------- pad: zero A padding rows + degree array ------------------
__global__ void pad_kernel() {
    int i = blockIdx.x * blockDim.x + threadIdx.x;
    if (i < NN) g_deg[i] = 0;
    int tot = (MP - NN) * 256;
    if (i < tot) {
        g_Ah[(size_t)NN * 256 + i] = __float2bfloat16(0.f);
        g_Al[(size_t)NN * 256 + i] = __float2bfloat16(0.f);
    }
}

// ---------------- edge list build (+self loops) + degree histogram ---------
__global__ void build_edges_kernel(const void* __restrict__ eiraw) {
    int i = blockIdx.x * blockDim.x + threadIdx.x;
    if (i >= ET) return;
    int s, d;
    if (i < EE) {
        if (g_is64) {
            const long long* e = (const long long*)eiraw;
            s = (int)e[i];
            d = (int)e[EE + i];
        } else {
            const int* e = (const int*)eiraw;
            s = e[i];
            d = e[EE + i];
        }
        s = min(max(s, 0), NN - 1);
        d = min(max(d, 0), NN - 1);
    } else {
        s = d = i - EE;   // self loop
    }
    g_src[i] = s;
    g_dst[i] = d;
    atomicAdd(&g_deg[d], 1);
}

// ---------------- CSR: 3-phase parallel scan + scatter ---------------------
__global__ void csr_partial_kernel() {
    __shared__ int sh[256];
    int idx = blockIdx.x * 256 + threadIdx.x;
    int v = (idx < NN) ? g_deg[idx] : 0;
    sh[threadIdx.x] = v;
    __syncthreads();
    for (int off = 128; off; off >>= 1) {
        if (threadIdx.x < off) sh[threadIdx.x] += sh[threadIdx.x + off];
        __syncthreads();
    }
    if (threadIdx.x == 0) g_bsum[blockIdx.x] = sh[0];
}

__global__ void csr_scanb_kernel() {
    if (threadIdx.x == 0) {
        int run = 0;
        for (int i = 0; i < NBLK; i++) { g_boff[i] = run; run += g_bsum[i]; }
        g_off[NN] = ET;
    }
}

__global__ void csr_offsets_kernel() {
    __shared__ int sh[256];
    int idx = blockIdx.x * 256 + threadIdx.x;
    int v = (idx < NN) ? g_deg[idx] : 0;
    sh[threadIdx.x] = v;
    __syncthreads();
    for (int off = 1; off < 256; off <<= 1) {
        int u = (threadIdx.x >= off) ? sh[threadIdx.x - off] : 0;
        __syncthreads();
        sh[threadIdx.x] += u;
        __syncthreads();
    }
    if (idx < NN) {
        int excl = g_boff[blockIdx.x] + sh[threadIdx.x] - v;
        g_off[idx] = excl;
        g_cur[idx] = excl;
    }
}

__global__ void scatter_kernel() {
    int i = blockIdx.x * blockDim.x + threadIdx.x;
    if (i >= ET) return;
    int d = g_dst[i];
    int pos = atomicAdd(&g_cur[d], 1);
    g_csr_src[pos] = g_src[i];
}

// ---------------- fp32 -> bf16 hi/lo split (x-features, vectorized) --------
__global__ void split_kernel(const float* __restrict__ X,
                             __nv_bfloat16* __restrict__ H,
                             __nv_bfloat16* __restrict__ L,
                             int realElems, int totElems) {
    int i = (blockIdx.x * blockDim.x + threadIdx.x) * 4;
    if (i >= totElems) return;
    float4 v = (i < realElems) ? *(const float4*)&X[i] : make_float4(0.f, 0.f, 0.f, 0.f);
    __nv_bfloat162 h01 = {__float2bfloat16(v.x), __float2bfloat16(v.y)};
    __nv_bfloat162 h23 = {__float2bfloat16(v.z), __float2bfloat16(v.w)};
    __nv_bfloat162 l01 = {__float2bfloat16(v.x - __bfloat162float(h01.x)),
                          __float2bfloat16(v.y - __bfloat162float(h01.y))};
    __nv_bfloat162 l23 = {__float2bfloat16(v.z - __bfloat162float(h23.x)),
                          __float2bfloat16(v.w - __bfloat162float(h23.y))};
    *(__nv_bfloat162*)&H[i] = h01;
    *(__nv_bfloat162*)&H[i + 2] = h23;
    *(__nv_bfloat162*)&L[i] = l01;
    *(__nv_bfloat162*)&L[i + 2] = l23;
}

// ---------------- ALL weight matrices split in one kernel ------------------
__global__ void wsplit_kernel(const float* __restrict__ W0, const float* __restrict__ rW0,
                              const float* __restrict__ W1, const float* __restrict__ W2,
                              const float* __restrict__ rW2) {
    int i4 = blockIdx.x * blockDim.x + threadIdx.x;    // float4 index
    if (i4 >= 98304) return;
    const float* src; int e4; size_t off;
    if (i4 < 4096)       { src = W0;  e4 = i4;         off = 0; }
    else if (i4 < 8192)  { src = rW0; e4 = i4 - 4096;  off = 16384; }
    else if (i4 < 24576) { src = W1;  e4 = i4 - 8192;  off = 32768; }
    else if (i4 < 90112) { src = W2;  e4 = i4 - 24576; off = 98304; }
    else                 { src = rW2; e4 = i4 - 90112; off = 360448; }
    float4 v = *(const float4*)&src[(size_t)e4 * 4];
    size_t o = off + (size_t)e4 * 4;
    __nv_bfloat162 h01 = {__float2bfloat16(v.x), __float2bfloat16(v.y)};
    __nv_bfloat162 h23 = {__float2bfloat16(v.z), __float2bfloat16(v.w)};
    __nv_bfloat162 l01 = {__float2bfloat16(v.x - __bfloat162float(h01.x)),
                          __float2bfloat16(v.y - __bfloat162float(h01.y))};
    __nv_bfloat162 l23 = {__float2bfloat16(v.z - __bfloat162float(h23.x)),
                          __float2bfloat16(v.w - __bfloat162float(h23.y))};
    *(__nv_bfloat162*)&g_Bh[o] = h01;
    *(__nv_bfloat162*)&g_Bh[o + 2] = h23;
    *(__nv_bfloat162*)&g_Bl[o] = l01;
    *(__nv_bfloat162*)&g_Bl[o + 2] = l23;
}

// ---------------- pipelined tensor-core GEMM -------------------------------
// C[MP,N] = A @ B, split-bf16 3-product, double-buffered cp.async stages.
// Block 128x128, BK=32, 8 warps (2x4), warp tile 64x32.
// Optional fp16 shadow written in the epilogue (Cf16 != nullptr).
#define STG 37888                    // bytes per stage
#define A_H_OFF 0                    // 128 x 40 halves = 10240 B
#define A_L_OFF 10240
#define B_H_OFF 20480                // 32 x 136 halves = 8704 B
#define B_L_OFF 29184

extern __shared__ char dynsm[];

__global__ void __launch_bounds__(256) gemm_tc_kernel(
    const __nv_bfloat16* __restrict__ Ah, const __nv_bfloat16* __restrict__ Al,
    const __nv_bfloat16* __restrict__ Bh, const __nv_bfloat16* __restrict__ Bl,
    float* __restrict__ C, __half* __restrict__ Cf16, int N, int K)
{
    char* sm = dynsm;
    unsigned smBase = (unsigned)__cvta_generic_to_shared(sm);
    int tid = threadIdx.x;
    int warp = tid >> 5;
    int wm = warp & 1, wn = warp >> 1;
    int row0 = blockIdx.y * 128, col0 = blockIdx.x * 128;

    wmma::fragment<wmma::accumulator, 16, 16, 16, float> acc[4][2];
#pragma unroll
    for (int i = 0; i < 4; i++)
#pragma unroll
        for (int j = 0; j < 2; j++) wmma::fill_fragment(acc[i][j], 0.f);

    const int nk = K >> 5;

    // stage loader: 8 cp.async (16B) per thread
    auto loadStage = [&](int s, int k0) {
        unsigned base = smBase + s * STG;
#pragma unroll
        for (int u = 0; u < 2; u++) {
            int v = tid + u * 256;
            int r = v >> 2, kk = v & 3;
            unsigned so = r * 80 + kk * 16;
            size_t g = (size_t)(row0 + r) * K + k0 + kk * 8;
            cp16(base + A_H_OFF + so, Ah + g);
            cp16(base + A_L_OFF + so, Al + g);
        }
#pragma unroll
        for (int u = 0; u < 2; u++) {
            int v = tid + u * 256;
            int r = v >> 4, cc = v & 15;
            unsigned so = r * 272 + cc * 16;
            size_t g = (size_t)(k0 + r) * N + col0 + cc * 8;
            cp16(base + B_H_OFF + so, Bh + g);
            cp16(base + B_L_OFF + so, Bl + g);
        }
    };

    loadStage(0, 0);
    cp_commit();

    for (int it = 0; it < nk; it++) {
        if (it + 1 < nk) loadStage((it + 1) & 1, (it + 1) * 32);
        cp_commit();
        cp_wait<1>();
        __syncthreads();
        char* st = sm + (it & 1) * STG;
        __nv_bfloat16* pAh = (__nv_bfloat16*)(st + A_H_OFF);
        __nv_bfloat16* pAl = (__nv_bfloat16*)(st + A_L_OFF);
        __nv_bfloat16* pBh = (__nv_bfloat16*)(st + B_H_OFF);
        __nv_bfloat16* pBl = (__nv_bfloat16*)(st + B_L_OFF);
#pragma unroll
        for (int ks = 0; ks < 32; ks += 16) {
            wmma::fragment<wmma::matrix_a, 16, 16, 16, __nv_bfloat16, wmma::row_major> fah[4], fal[4];
            wmma::fragment<wmma::matrix_b, 16, 16, 16, __nv_bfloat16, wmma::row_major> fbh[2], fbl[2];
#pragma unroll
            for (int i = 0; i < 4; i++) {
                wmma::load_matrix_sync(fah[i], pAh + (wm * 64 + i * 16) * 40 + ks, 40);
                wmma::load_matrix_sync(fal[i], pAl + (wm * 64 + i * 16) * 40 + ks, 40);
            }
#pragma unroll
            for (int j = 0; j < 2; j++) {
                wmma::load_matrix_sync(fbh[j], pBh + ks * 136 + wn * 32 + j * 16, 136);
                wmma::load_matrix_sync(fbl[j], pBl + ks * 136 + wn * 32 + j * 16, 136);
            }
#pragma unroll
            for (int i = 0; i < 4; i++)
#pragma unroll
                for (int j = 0; j < 2; j++) {
                    wmma::mma_sync(acc[i][j], fah[i], fbh[j], acc[i][j]);
                    wmma::mma_sync(acc[i][j], fal[i], fbh[j], acc[i][j]);
                    wmma::mma_sync(acc[i][j], fah[i], fbl[j], acc[i][j]);
                }
        }
        __syncthreads();
    }

#pragma unroll
    for (int i = 0; i < 4; i++)
#pragma unroll
        for (int j = 0; j < 2; j++)
            wmma::store_matrix_sync(&C[(size_t)(row0 + wm * 64 + i * 16) * N +
                                       col0 + wn * 32 + j * 16],
                                    acc[i][j], N, wmma::mem_row_major);

    if (Cf16) {
        __syncthreads();   // block-scope fence: other warps' C stores visible (same SM/L1)
        for (int idx = tid; idx < 4096; idx += 256) {
            int r = idx >> 5, cch = idx & 31;
            size_t g = (size_t)(row0 + r) * N + col0 + cch * 4;
            float4 v = *(const float4*)&C[g];
            __half2 a = __floats2half2_rn(v.x, v.y);
            __half2 b = __floats2half2_rn(v.z, v.w);
            *(__half2*)&Cf16[g] = a;
            *(__half2*)&Cf16[g + 2] = b;
        }
    }
}

// ---------------- attention logits: al_s/al_d per (node, head) -------------
__global__ void al_kernel(const float* __restrict__ a_s, const float* __restrict__ a_d, int C) {
    int idx = blockIdx.x * blockDim.x + threadIdx.x;
    if (idx >= NN * HEADS) return;
    int n = idx >> 3, h = idx & 7;
    const float* f = g_feat + (size_t)n * HEADS * C + h * C;
    const float* w1 = a_s + h * C;
    const float* w2 = a_d + h * C;
    float s1 = 0.f, s2 = 0.f;
    for (int c = 0; c < C; c++) { float v = f[c]; s1 += v * w1[c]; s2 += v * w2[c]; }
    g_als[idx] = s1;
    g_ald[idx] = s2;
}

// ---------------- fused aggregation (layers 0/1, C=32), warp per dst -------
__global__ void __launch_bounds__(256) agg_small_kernel(const __half* __restrict__ feath,
                                                        float* __restrict__ out) {
    int wid = (blockIdx.x * blockDim.x + threadIdx.x) >> 5;
    if (wid >= NN) return;
    int lane = threadIdx.x & 31;
    int h = lane & 7;
    int beg = g_off[wid], end = g_off[wid + 1];
    float ald_h = g_ald[wid * HEADS + h];

    float m = -1e30f;
    for (int i = beg + (lane >> 3); i < end; i += 4) {
        int s = g_csr_src[i];
        float ev = g_als[s * HEADS + h] + ald_h;
        ev = ev > 0.f ? ev : 0.2f * ev;
        m = fmaxf(m, ev);
    }
    m = fmaxf(m, __shfl_xor_sync(0xffffffffu, m, 8));
    m = fmaxf(m, __shfl_xor_sync(0xffffffffu, m, 16));
    float ssum = 0.f;
    for (int i = beg + (lane >> 3); i < end; i += 4) {
        int s = g_csr_src[i];
        float ev = g_als[s * HEADS + h] + ald_h;
        ev = ev > 0.f ? ev : 0.2f * ev;
        ssum += expf(ev - m);
    }
    ssum += __shfl_xor_sync(0xffffffffu, ssum, 8);
    ssum += __shfl_xor_sync(0xffffffffu, ssum, 16);
    float inv = 1.f / (ssum + 1e-16f);

    float acc[8] = {0.f, 0.f, 0.f, 0.f, 0.f, 0.f, 0.f, 0.f};
    for (int i = beg; i < end; i++) {
        int s = g_csr_src[i];
        float ev = g_als[s * HEADS + h] + ald_h;
        ev = ev > 0.f ? ev : 0.2f * ev;
        float alpha = expf(ev - m) * inv;
        const __half* f = feath + (size_t)s * 256;
#pragma unroll
        for (int hh = 0; hh < 8; hh++) {
            float a = __shfl_sync(0xffffffffu, alpha, hh);
            acc[hh] += a * __half2float(f[hh * 32 + lane]);
        }
    }
    float* o = out + (size_t)wid * 256;
#pragma unroll
    for (int hh = 0; hh < 8; hh++) o[hh * 32 + lane] = acc[hh];
}

// ---------------- fused aggregation (layer 2, C=128, mean over heads) ------
__global__ void __launch_bounds__(256) agg_big_kernel(const __half* __restrict__ feath,
                                                      float* __restrict__ out) {
    int wid = (blockIdx.x * blockDim.x + threadIdx.x) >> 5;
    if (wid >= NN) return;
    int lane = threadIdx.x & 31;
    int h = lane & 7;
    int beg = g_off[wid], end = g_off[wid + 1];
    float ald_h = g_ald[wid * HEADS + h];

    float m = -1e30f;
    for (int i = beg + (lane >> 3); i < end; i += 4) {
        int s = g_csr_src[i];
        float ev = g_als[s * HEADS + h] + ald_h;
        ev = ev > 0.f ? ev : 0.2f * ev;
        m = fmaxf(m, ev);
    }
    m = fmaxf(m, __shfl_xor_sync(0xffffffffu, m, 8));
    m = fmaxf(m, __shfl_xor_sync(0xffffffffu, m, 16));
    float ssum = 0.f;
    for (int i = beg + (lane >> 3); i < end; i += 4) {
        int s = g_csr_src[i];
        float ev = g_als[s * HEADS + h] + ald_h;
        ev = ev > 0.f ? ev : 0.2f * ev;
        ssum += expf(ev - m);
    }
    ssum += __shfl_xor_sync(0xffffffffu, ssum, 8);
    ssum += __shfl_xor_sync(0xffffffffu, ssum, 16);
    float inv = 0.125f / (ssum + 1e-16f);

    float acc[4] = {0.f, 0.f, 0.f, 0.f};
    for (int i = beg; i < end; i++) {
        int s = g_csr_src[i];
        float ev = g_als[s * HEADS + h] + ald_h;
        ev = ev > 0.f ? ev : 0.2f * ev;
        float alpha = expf(ev - m) * inv;
        const __half* f = feath + (size_t)s * 1024;
#pragma unroll
        for (int hh = 0; hh < 8; hh++) {
            float a = __shfl_sync(0xffffffffu, alpha, hh);
            const __half* fh = f + hh * 128;
#pragma unroll
            for (int ch = 0; ch < 4; ch++)
                acc[ch] += a * __half2float(fh[ch * 32 + lane]);
        }
    }
    float* o = out + (size_t)wid * 128;
#pragma unroll
    for (int ch = 0; ch < 4; ch++) o[ch * 32 + lane] = acc[ch];
}

// ---------------- finalize layers 0/1: +bias, LN, +sig*res, ELU + split ----
__global__ void finalize01_kernel(const float* __restrict__ bias,
                                  const float* __restrict__ lng, const float* __restrict__ lnb,
                                  const float* __restrict__ res, const float* __restrict__ rb,
                                  const float* __restrict__ rw, float* __restrict__ out,
                                  __nv_bfloat16* __restrict__ outH,
                                  __nv_bfloat16* __restrict__ outL) {
    int n = blockIdx.x, t = threadIdx.x;   // 256 threads
    float g = g_accb[(size_t)n * 256 + t] + bias[t];
    float s1 = g, s2 = g * g;
#pragma unroll
    for (int o = 16; o; o >>= 1) {
        s1 += __shfl_down_sync(0xffffffffu, s1, o);
        s2 += __shfl_down_sync(0xffffffffu, s2, o);
    }
    __shared__ float sh1[8], sh2[8];
    __shared__ float mu_s, rs_s;
    int w = t >> 5, l = t & 31;
    if (l == 0) { sh1[w] = s1; sh2[w] = s2; }
    __syncthreads();
    if (t == 0) {
        float a = 0.f, b = 0.f;
#pragma unroll
        for (int i = 0; i < 8; i++) { a += sh1[i]; b += sh2[i]; }
        float mu = a * (1.f / 256.f);
        float var = b * (1.f / 256.f) - mu * mu;
        mu_s = mu;
        rs_s = rsqrtf(var + 1e-5f);
    }
    __syncthreads();
    float y = (g - mu_s) * rs_s * lng[t] + lnb[t];
    float sig = 1.f / (1.f + expf(-rw[0]));
    float r = res[(size_t)n * 256 + t];
    if (rb) r += rb[t];
    float z = y + sig * r;
    z = z > 0.f ? z : expm1f(z);   // elu
    size_t o = (size_t)n * 256 + t;
    out[o] = z;
    __nv_bfloat16 zh = __float2bfloat16(z);
    outH[o] = zh;
    outL[o] = __float2bfloat16(z - __bfloat162float(zh));
}

// ---------------- finalize layer 2: +bias, LN, +sig*res (no elu) -----------
__global__ void finalize2_kernel(const float* __restrict__ bias,
                                 const float* __restrict__ lng, const float* __restrict__ lnb,
                                 const float* __restrict__ res, const float* __restrict__ rb,
                                 const float* __restrict__ rw, float* __restrict__ out) {
    int n = blockIdx.x, t = threadIdx.x;   // 128 threads
    float g = g_accb[(size_t)n * 128 + t] + bias[t];
    float s1 = g, s2 = g * g;
#pragma unroll
    for (int o = 16; o; o >>= 1) {
        s1 += __shfl_down_sync(0xffffffffu, s1, o);
        s2 += __shfl_down_sync(0xffffffffu, s2, o);
    }
    __shared__ float sh1[4], sh2[4];
    __shared__ float mu_s, rs_s;
    int w = t >> 5, l = t & 31;
    if (l == 0) { sh1[w] = s1; sh2[w] = s2; }
    __syncthreads();
    if (t == 0) {
        float a = 0.f, b = 0.f;
#pragma unroll
        for (int i = 0; i < 4; i++) { a += sh1[i]; b += sh2[i]; }
        float mu = a * (1.f / 128.f);
        float var = b * (1.f / 128.f) - mu * mu;
        mu_s = mu;
        rs_s = rsqrtf(var + 1e-5f);
    }
    __syncthreads();
    float y = (g - mu_s) * rs_s * lng[t] + lnb[t];
    float sig = 1.f / (1.f + expf(-rw[0]));
    float r = res[(size_t)n * 128 + t] + rb[t];
    out[(size_t)n * 128 + t] = y + sig * r;
}

// ---------------------------------------------------------------------------
extern "C" void kernel_launch(void* const* d_in, const int* in_sizes, int n_in,
                              void* d_out, int out_size) {
    const float* x   = (const float*)d_in[0];
    const void*  ei  = d_in[1];                   // int32 or int64, detected on device
    const float* W0  = (const float*)d_in[2];
    const float* b0  = (const float*)d_in[3];
    const float* as0 = (const float*)d_in[4];
    const float* ad0 = (const float*)d_in[5];
    const float* lng0= (const float*)d_in[6];
    const float* lnb0= (const float*)d_in[7];
    const float* rW0 = (const float*)d_in[8];
    const float* rb0 = (const float*)d_in[9];
    const float* rw0 = (const float*)d_in[10];
    const float* W1  = (const float*)d_in[11];
    const float* b1  = (const float*)d_in[12];
    const float* as1 = (const float*)d_in[13];
    const float* ad1 = (const float*)d_in[14];
    const float* lng1= (const float*)d_in[15];
    const float* lnb1= (const float*)d_in[16];
    const float* rw1 = (const float*)d_in[17];
    const float* W2  = (const float*)d_in[18];
    const float* b2  = (const float*)d_in[19];
    const float* as2 = (const float*)d_in[20];
    const float* ad2 = (const float*)d_in[21];
    const float* lng2= (const float*)d_in[22];
    const float* lnb2= (const float*)d_in[23];
    const float* rW2 = (const float*)d_in[24];
    const float* rb2 = (const float*)d_in[25];
    const float* rw2 = (const float*)d_in[26];

    float *feat, *act0, *act1, *res, *accb;
    __half *feath;
    __nv_bfloat16 *Ah, *Al, *Bh, *Bl;
    cudaGetSymbolAddress((void**)&feat, g_feat);
    cudaGetSymbolAddress((void**)&feath, g_feath);
    cudaGetSymbolAddress((void**)&act0, g_act0);
    cudaGetSymbolAddress((void**)&act1, g_act1);
    cudaGetSymbolAddress((void**)&res,  g_resb);
    cudaGetSymbolAddress((void**)&accb, g_accb);
    cudaGetSymbolAddress((void**)&Ah, g_Ah);
    cudaGetSymbolAddress((void**)&Al, g_Al);
    cudaGetSymbolAddress((void**)&Bh, g_Bh);
    cudaGetSymbolAddress((void**)&Bl, g_Bl);

    static bool attrSet = false;
    if (!attrSet) {
        cudaFuncSetAttribute(gemm_tc_kernel,
                             cudaFuncAttributeMaxDynamicSharedMemorySize, 2 * STG);
        attrSet = true;
    }

    const int TB = 256;
    detect_kernel<<<1, 256>>>((const int*)ei);
    pad_kernel<<<((MP - NN) * 256 + TB - 1) / TB, TB>>>();
    build_edges_kernel<<<(ET + TB - 1) / TB, TB>>>(ei);
    csr_partial_kernel<<<NBLK, 256>>>();
    csr_scanb_kernel<<<1, 32>>>();
    csr_offsets_kernel<<<NBLK, 256>>>();
    scatter_kernel<<<(ET + TB - 1) / TB, TB>>>();
    wsplit_kernel<<<(98304 + TB - 1) / TB, TB>>>(W0, rW0, W1, W2, rW2);
    split_kernel<<<(MP * 64 / 4 + TB - 1) / TB, TB>>>(x, Ah, Al, NN * 64, MP * 64);

    int alBlocks  = (NN * HEADS + TB - 1) / TB;
    int aggBlocks = (NN * 32 + TB - 1) / TB;
    const int MROWS = MP / 128;   // 157
    const size_t SM = 2 * STG;

    // ---------------- layer 0 ----------------
    gemm_tc_kernel<<<dim3(2, MROWS), 256, SM>>>(Ah, Al, Bh, Bl, feat, feath, 256, 64);
    gemm_tc_kernel<<<dim3(2, MROWS), 256, SM>>>(Ah, Al, Bh + 16384, Bl + 16384, res, nullptr, 256, 64);
    al_kernel<<<alBlocks, TB>>>(as0, ad0, 32);
    agg_small_kernel<<<aggBlocks, TB>>>(feath, accb);
    finalize01_kernel<<<NN, 256>>>(b0, lng0, lnb0, res, rb0, rw0, act0, Ah, Al);

    // ---------------- layer 1 ----------------
    gemm_tc_kernel<<<dim3(2, MROWS), 256, SM>>>(Ah, Al, Bh + 32768, Bl + 32768, feat, feath, 256, 256);
    al_kernel<<<alBlocks, TB>>>(as1, ad1, 32);
    agg_small_kernel<<<aggBlocks, TB>>>(feath, accb);
    finalize01_kernel<<<NN, 256>>>(b1, lng1, lnb1, act0, nullptr, rw1, act1, Ah, Al);

    // ---------------- layer 2 ----------------
    gemm_tc_kernel<<<dim3(8, MROWS), 256, SM>>>(Ah, Al, Bh + 98304, Bl + 98304, feat, feath, 1024, 256);
    gemm_tc_kernel<<<dim3(1, MROWS), 256, SM>>>(Ah, Al, Bh + 360448, Bl + 360448, res, nullptr, 128, 256);
    al_kernel<<<alBlocks, TB>>>(as2, ad2, 128);
    agg_big_kernel<<<aggBlocks, TB>>>(feath, accb);
    finalize2_kernel<<<NN, 128>>>(b2, lng2, lnb2, res, rb2, rw2, (float*)d_out);
}

// round 11
// speedup vs baseline: 1.6701x; 1.6701x over previous
#include <cuda_runtime.h>
#include <cuda_bf16.h>
#include <cuda_fp16.h>
#include <cstdint>
#include <mma.h>
using namespace nvcuda;

// Problem constants (fixed by the reference)
#define NN 20000
#define EE 320000
#define ET (NN + EE)          // edges incl. self loops = 340000
#define HEADS 8
#define MP 20096              // NN padded to multiple of 128 for tensor GEMM
#define NBLK ((NN + 255) / 256)   // 79 blocks for CSR scan

// ---------------- scratch (device globals: no allocation allowed) ----------
__device__ float g_feat[(size_t)MP * 1024];   // transformed features (fp32)
__device__ __half g_feath[(size_t)MP * 1024]; // fp16 shadow for gathers
__device__ float g_accb[(size_t)NN * 256];    // aggregation output
__device__ float g_act0[(size_t)NN * 256];    // activation after layer 0
__device__ float g_act1[(size_t)NN * 256];    // activation after layer 1
__device__ float g_resb[(size_t)MP * 256];    // residual projection
__device__ float g_als[NN * HEADS];
__device__ float g_ald[NN * HEADS];
__device__ int g_src[ET];
__device__ int g_dst[ET];
__device__ int g_is64;
// CSR (dst-sorted adjacency)
__device__ int g_deg[NN];
__device__ int g_off[NN + 1];
__device__ int g_cur[NN];
__device__ int g_csr_src[ET];
__device__ int g_bsum[NBLK];
__device__ int g_boff[NBLK];

// bf16 split buffers. A: activations (MP x 256 max). B: ALL weights, segmented:
//   W0 @ 0 (16384), rW0 @ 16384 (16384), W1 @ 32768 (65536),
//   W2 @ 98304 (262144), rW2 @ 360448 (32768)  -> total 393216 elems
__device__ __nv_bfloat16 g_Ah[(size_t)MP * 256];
__device__ __nv_bfloat16 g_Al[(size_t)MP * 256];
__device__ __nv_bfloat16 g_Bh[393216];
__device__ __nv_bfloat16 g_Bl[393216];

// ---------------- dtype detection: int64 vs int32 edge_index ---------------
__global__ void detect_kernel(const int* __restrict__ raw) {
    __shared__ int any;
    if (threadIdx.x == 0) any = 0;
    __syncthreads();
    for (int i = threadIdx.x; i < 2048; i += blockDim.x)
        if (raw[2 * i + 1] != 0) any = 1;
    __syncthreads();
    if (threadIdx.x == 0) g_is64 = (any == 0);
}

// ---------------- pad: zero A padding rows + degree array ------------------
__global__ void pad_kernel() {
    int i = blockIdx.x * blockDim.x + threadIdx.x;
    if (i < NN) g_deg[i] = 0;
    int tot = (MP - NN) * 256;
    if (i < tot) {
        g_Ah[(size_t)NN * 256 + i] = __float2bfloat16(0.f);
        g_Al[(size_t)NN * 256 + i] = __float2bfloat16(0.f);
    }
}

// ---------------- edge list build (+self loops) + degree histogram ---------
__global__ void build_edges_kernel(const void* __restrict__ eiraw) {
    int i = blockIdx.x * blockDim.x + threadIdx.x;
    if (i >= ET) return;
    int s, d;
    if (i < EE) {
        if (g_is64) {
            const long long* e = (const long long*)eiraw;
            s = (int)e[i];
            d = (int)e[EE + i];
        } else {
            const int* e = (const int*)eiraw;
            s = e[i];
            d = e[EE + i];
        }
        s = min(max(s, 0), NN - 1);
        d = min(max(d, 0), NN - 1);
    } else {
        s = d = i - EE;   // self loop
    }
    g_src[i] = s;
    g_dst[i] = d;
    atomicAdd(&g_deg[d], 1);
}

// ---------------- CSR: 3-phase parallel scan + scatter ---------------------
__global__ void csr_partial_kernel() {
    __shared__ int sh[256];
    int idx = blockIdx.x * 256 + threadIdx.x;
    int v = (idx < NN) ? g_deg[idx] : 0;
    sh[threadIdx.x] = v;
    __syncthreads();
    for (int off = 128; off; off >>= 1) {
        if (threadIdx.x < off) sh[threadIdx.x] += sh[threadIdx.x + off];
        __syncthreads();
    }
    if (threadIdx.x == 0) g_bsum[blockIdx.x] = sh[0];
}

__global__ void csr_scanb_kernel() {
    if (threadIdx.x == 0) {
        int run = 0;
        for (int i = 0; i < NBLK; i++) { g_boff[i] = run; run += g_bsum[i]; }
        g_off[NN] = ET;
    }
}

__global__ void csr_offsets_kernel() {
    __shared__ int sh[256];
    int idx = blockIdx.x * 256 + threadIdx.x;
    int v = (idx < NN) ? g_deg[idx] : 0;
    sh[threadIdx.x] = v;
    __syncthreads();
    for (int off = 1; off < 256; off <<= 1) {
        int u = (threadIdx.x >= off) ? sh[threadIdx.x - off] : 0;
        __syncthreads();
        sh[threadIdx.x] += u;
        __syncthreads();
    }
    if (idx < NN) {
        int excl = g_boff[blockIdx.x] + sh[threadIdx.x] - v;
        g_off[idx] = excl;
        g_cur[idx] = excl;
    }
}

__global__ void scatter_kernel() {
    int i = blockIdx.x * blockDim.x + threadIdx.x;
    if (i >= ET) return;
    int d = g_dst[i];
    int pos = atomicAdd(&g_cur[d], 1);
    g_csr_src[pos] = g_src[i];
}

// ---------------- fp32 -> bf16 hi/lo split (x-features, vectorized) --------
__global__ void split_kernel(const float* __restrict__ X,
                             __nv_bfloat16* __restrict__ H,
                             __nv_bfloat16* __restrict__ L,
                             int realElems, int totElems) {
    int i = (blockIdx.x * blockDim.x + threadIdx.x) * 4;
    if (i >= totElems) return;
    float4 v = (i < realElems) ? *(const float4*)&X[i] : make_float4(0.f, 0.f, 0.f, 0.f);
    __nv_bfloat162 h01 = {__float2bfloat16(v.x), __float2bfloat16(v.y)};
    __nv_bfloat162 h23 = {__float2bfloat16(v.z), __float2bfloat16(v.w)};
    __nv_bfloat162 l01 = {__float2bfloat16(v.x - __bfloat162float(h01.x)),
                          __float2bfloat16(v.y - __bfloat162float(h01.y))};
    __nv_bfloat162 l23 = {__float2bfloat16(v.z - __bfloat162float(h23.x)),
                          __float2bfloat16(v.w - __bfloat162float(h23.y))};
    *(__nv_bfloat162*)&H[i] = h01;
    *(__nv_bfloat162*)&H[i + 2] = h23;
    *(__nv_bfloat162*)&L[i] = l01;
    *(__nv_bfloat162*)&L[i + 2] = l23;
}

// ---------------- ALL weight matrices split in one kernel ------------------
__global__ void wsplit_kernel(const float* __restrict__ W0, const float* __restrict__ rW0,
                              const float* __restrict__ W1, const float* __restrict__ W2,
                              const float* __restrict__ rW2) {
    int i4 = blockIdx.x * blockDim.x + threadIdx.x;    // float4 index
    if (i4 >= 98304) return;
    const float* src; int e4; size_t off;
    if (i4 < 4096)       { src = W0;  e4 = i4;         off = 0; }
    else if (i4 < 8192)  { src = rW0; e4 = i4 - 4096;  off = 16384; }
    else if (i4 < 24576) { src = W1;  e4 = i4 - 8192;  off = 32768; }
    else if (i4 < 90112) { src = W2;  e4 = i4 - 24576; off = 98304; }
    else                 { src = rW2; e4 = i4 - 90112; off = 360448; }
    float4 v = *(const float4*)&src[(size_t)e4 * 4];
    size_t o = off + (size_t)e4 * 4;
    __nv_bfloat162 h01 = {__float2bfloat16(v.x), __float2bfloat16(v.y)};
    __nv_bfloat162 h23 = {__float2bfloat16(v.z), __float2bfloat16(v.w)};
    __nv_bfloat162 l01 = {__float2bfloat16(v.x - __bfloat162float(h01.x)),
                          __float2bfloat16(v.y - __bfloat162float(h01.y))};
    __nv_bfloat162 l23 = {__float2bfloat16(v.z - __bfloat162float(h23.x)),
                          __float2bfloat16(v.w - __bfloat162float(h23.y))};
    *(__nv_bfloat162*)&g_Bh[o] = h01;
    *(__nv_bfloat162*)&g_Bh[o + 2] = h23;
    *(__nv_bfloat162*)&g_Bl[o] = l01;
    *(__nv_bfloat162*)&g_Bl[o + 2] = l23;
}

// ---------------- tensor-core GEMM (static smem, high occupancy) -----------
// C[MP,N] = A @ B, split-bf16 3-product. Block 128x128, BK=32, 8 warps.
// Optional fp16 shadow written in the epilogue (Cf16 != nullptr).
struct __align__(256) SmemA { __nv_bfloat16 d[128][40]; };
struct __align__(256) SmemB { __nv_bfloat16 d[32][136]; };

__global__ void __launch_bounds__(256) gemm_tc_kernel(
    const __nv_bfloat16* __restrict__ Ah, const __nv_bfloat16* __restrict__ Al,
    const __nv_bfloat16* __restrict__ Bh, const __nv_bfloat16* __restrict__ Bl,
    float* __restrict__ C, __half* __restrict__ Cf16, int N, int K)
{
    __shared__ SmemA sAh, sAl;
    __shared__ SmemB sBh, sBl;
    int tid = threadIdx.x;
    int warp = tid >> 5;
    int wm = warp & 1, wn = warp >> 1;           // 2 x 4 warp grid
    int row0 = blockIdx.y * 128, col0 = blockIdx.x * 128;

    wmma::fragment<wmma::accumulator, 16, 16, 16, float> acc[4][2];
#pragma unroll
    for (int i = 0; i < 4; i++)
#pragma unroll
        for (int j = 0; j < 2; j++) wmma::fill_fragment(acc[i][j], 0.f);

    for (int k0 = 0; k0 < K; k0 += 32) {
#pragma unroll
        for (int v = tid; v < 512; v += 256) {
            int r = v >> 2, kk = (v & 3) * 8;
            size_t g = (size_t)(row0 + r) * K + k0 + kk;
            *(uint4*)&sAh.d[r][kk] = *(const uint4*)&Ah[g];
            *(uint4*)&sAl.d[r][kk] = *(const uint4*)&Al[g];
        }
#pragma unroll
        for (int v = tid; v < 512; v += 256) {
            int r = v >> 4, cc = (v & 15) * 8;
            size_t g = (size_t)(k0 + r) * N + col0 + cc;
            *(uint4*)&sBh.d[r][cc] = *(const uint4*)&Bh[g];
            *(uint4*)&sBl.d[r][cc] = *(const uint4*)&Bl[g];
        }
        __syncthreads();
#pragma unroll
        for (int ks = 0; ks < 32; ks += 16) {
            wmma::fragment<wmma::matrix_a, 16, 16, 16, __nv_bfloat16, wmma::row_major> fah[4], fal[4];
            wmma::fragment<wmma::matrix_b, 16, 16, 16, __nv_bfloat16, wmma::row_major> fbh[2], fbl[2];
#pragma unroll
            for (int i = 0; i < 4; i++) {
                wmma::load_matrix_sync(fah[i], &sAh.d[wm * 64 + i * 16][ks], 40);
                wmma::load_matrix_sync(fal[i], &sAl.d[wm * 64 + i * 16][ks], 40);
            }
#pragma unroll
            for (int j = 0; j < 2; j++) {
                wmma::load_matrix_sync(fbh[j], &sBh.d[ks][wn * 32 + j * 16], 136);
                wmma::load_matrix_sync(fbl[j], &sBl.d[ks][wn * 32 + j * 16], 136);
            }
#pragma unroll
            for (int i = 0; i < 4; i++)
#pragma unroll
                for (int j = 0; j < 2; j++) {
                    wmma::mma_sync(acc[i][j], fah[i], fbh[j], acc[i][j]);
                    wmma::mma_sync(acc[i][j], fal[i], fbh[j], acc[i][j]);
                    wmma::mma_sync(acc[i][j], fah[i], fbl[j], acc[i][j]);
                }
        }
        __syncthreads();
    }
#pragma unroll
    for (int i = 0; i < 4; i++)
#pragma unroll
        for (int j = 0; j < 2; j++)
            wmma::store_matrix_sync(&C[(size_t)(row0 + wm * 64 + i * 16) * N +
                                       col0 + wn * 32 + j * 16],
                                    acc[i][j], N, wmma::mem_row_major);

    if (Cf16) {
        __syncthreads();   // other warps' C stores visible (same SM/L1)
        for (int idx = tid; idx < 4096; idx += 256) {
            int r = idx >> 5, cch = idx & 31;
            size_t g = (size_t)(row0 + r) * N + col0 + cch * 4;
            float4 v = *(const float4*)&C[g];
            __half2 a = __floats2half2_rn(v.x, v.y);
            __half2 b = __floats2half2_rn(v.z, v.w);
            *(__half2*)&Cf16[g] = a;
            *(__half2*)&Cf16[g + 2] = b;
        }
    }
}

// ---------------- attention logits, warp per node (coalesced) --------------
// C=32: row = 256 floats; lane handles elems [lane*8, lane*8+8), head = lane/4.
__global__ void al_small_kernel(const float* __restrict__ a_s, const float* __restrict__ a_d) {
    int node = (blockIdx.x * blockDim.x + threadIdx.x) >> 5;
    if (node >= NN) return;
    int lane = threadIdx.x & 31;
    const float4* f = (const float4*)(g_feat + (size_t)node * 256) + lane * 2;
    const float4* ws = (const float4*)a_s + lane * 2;
    const float4* wd = (const float4*)a_d + lane * 2;
    float4 v0 = f[0], v1 = f[1];
    float4 w0 = ws[0], w1 = ws[1];
    float4 u0 = wd[0], u1 = wd[1];
    float s1 = v0.x * w0.x + v0.y * w0.y + v0.z * w0.z + v0.w * w0.w
             + v1.x * w1.x + v1.y * w1.y + v1.z * w1.z + v1.w * w1.w;
    float s2 = v0.x * u0.x + v0.y * u0.y + v0.z * u0.z + v0.w * u0.w
             + v1.x * u1.x + v1.y * u1.y + v1.z * u1.z + v1.w * u1.w;
    s1 += __shfl_xor_sync(0xffffffffu, s1, 1);
    s1 += __shfl_xor_sync(0xffffffffu, s1, 2);
    s2 += __shfl_xor_sync(0xffffffffu, s2, 1);
    s2 += __shfl_xor_sync(0xffffffffu, s2, 2);
    if ((lane & 3) == 0) {
        int h = lane >> 2;
        g_als[node * 8 + h] = s1;
        g_ald[node * 8 + h] = s2;
    }
}

// C=128: row = 1024 floats; lane handles elems [lane*32, lane*32+32), head = lane/4.
__global__ void al_big_kernel(const float* __restrict__ a_s, const float* __restrict__ a_d) {
    int node = (blockIdx.x * blockDim.x + threadIdx.x) >> 5;
    if (node >= NN) return;
    int lane = threadIdx.x & 31;
    const float4* f = (const float4*)(g_feat + (size_t)node * 1024) + lane * 8;
    const float4* ws = (const float4*)a_s + lane * 8;
    const float4* wd = (const float4*)a_d + lane * 8;
    float s1 = 0.f, s2 = 0.f;
#pragma unroll
    for (int j = 0; j < 8; j++) {
        float4 v = f[j], w = ws[j], u = wd[j];
        s1 += v.x * w.x + v.y * w.y + v.z * w.z + v.w * w.w;
        s2 += v.x * u.x + v.y * u.y + v.z * u.z + v.w * u.w;
    }
    s1 += __shfl_xor_sync(0xffffffffu, s1, 1);
    s1 += __shfl_xor_sync(0xffffffffu, s1, 2);
    s2 += __shfl_xor_sync(0xffffffffu, s2, 1);
    s2 += __shfl_xor_sync(0xffffffffu, s2, 2);
    if ((lane & 3) == 0) {
        int h = lane >> 2;
        g_als[node * 8 + h] = s1;
        g_ald[node * 8 + h] = s2;
    }
}

// ---------------- fused aggregation (layers 0/1, C=32), warp per dst -------
__global__ void __launch_bounds__(256) agg_small_kernel(const __half* __restrict__ feath,
                                                        float* __restrict__ out) {
    int wid = (blockIdx.x * blockDim.x + threadIdx.x) >> 5;
    if (wid >= NN) return;
    int lane = threadIdx.x & 31;
    int h = lane & 7;
    int beg = g_off[wid], end = g_off[wid + 1];
    float ald_h = g_ald[wid * HEADS + h];

    float m = -1e30f;
    for (int i = beg + (lane >> 3); i < end; i += 4) {
        int s = g_csr_src[i];
        float ev = g_als[s * HEADS + h] + ald_h;
        ev = ev > 0.f ? ev : 0.2f * ev;
        m = fmaxf(m, ev);
    }
    m = fmaxf(m, __shfl_xor_sync(0xffffffffu, m, 8));
    m = fmaxf(m, __shfl_xor_sync(0xffffffffu, m, 16));
    float ssum = 0.f;
    for (int i = beg + (lane >> 3); i < end; i += 4) {
        int s = g_csr_src[i];
        float ev = g_als[s * HEADS + h] + ald_h;
        ev = ev > 0.f ? ev : 0.2f * ev;
        ssum += expf(ev - m);
    }
    ssum += __shfl_xor_sync(0xffffffffu, ssum, 8);
    ssum += __shfl_xor_sync(0xffffffffu, ssum, 16);
    float inv = 1.f / (ssum + 1e-16f);

    float acc[8] = {0.f, 0.f, 0.f, 0.f, 0.f, 0.f, 0.f, 0.f};
    for (int i = beg; i < end; i++) {
        int s = g_csr_src[i];
        float ev = g_als[s * HEADS + h] + ald_h;
        ev = ev > 0.f ? ev : 0.2f * ev;
        float alpha = expf(ev - m) * inv;
        const __half* f = feath + (size_t)s * 256;
#pragma unroll
        for (int hh = 0; hh < 8; hh++) {
            float a = __shfl_sync(0xffffffffu, alpha, hh);
            acc[hh] += a * __half2float(f[hh * 32 + lane]);
        }
    }
    float* o = out + (size_t)wid * 256;
#pragma unroll
    for (int hh = 0; hh < 8; hh++) o[hh * 32 + lane] = acc[hh];
}

// ---------------- fused aggregation (layer 2, C=128, mean over heads) ------
__global__ void __launch_bounds__(256) agg_big_kernel(const __half* __restrict__ feath,
                                                      float* __restrict__ out) {
    int wid = (blockIdx.x * blockDim.x + threadIdx.x) >> 5;
    if (wid >= NN) return;
    int lane = threadIdx.x & 31;
    int h = lane & 7;
    int beg = g_off[wid], end = g_off[wid + 1];
    float ald_h = g_ald[wid * HEADS + h];

    float m = -1e30f;
    for (int i = beg + (lane >> 3); i < end; i += 4) {
        int s = g_csr_src[i];
        float ev = g_als[s * HEADS + h] + ald_h;
        ev = ev > 0.f ? ev : 0.2f * ev;
        m = fmaxf(m, ev);
    }
    m = fmaxf(m, __shfl_xor_sync(0xffffffffu, m, 8));
    m = fmaxf(m, __shfl_xor_sync(0xffffffffu, m, 16));
    float ssum = 0.f;
    for (int i = beg + (lane >> 3); i < end; i += 4) {
        int s = g_csr_src[i];
        float ev = g_als[s * HEADS + h] + ald_h;
        ev = ev > 0.f ? ev : 0.2f * ev;
        ssum += expf(ev - m);
    }
    ssum += __shfl_xor_sync(0xffffffffu, ssum, 8);
    ssum += __shfl_xor_sync(0xffffffffu, ssum, 16);
    float inv = 0.125f / (ssum + 1e-16f);

    float acc[4] = {0.f, 0.f, 0.f, 0.f};
    for (int i = beg; i < end; i++) {
        int s = g_csr_src[i];
        float ev = g_als[s * HEADS + h] + ald_h;
        ev = ev > 0.f ? ev : 0.2f * ev;
        float alpha = expf(ev - m) * inv;
        const __half* f = feath + (size_t)s * 1024;
#pragma unroll
        for (int hh = 0; hh < 8; hh++) {
            float a = __shfl_sync(0xffffffffu, alpha, hh);
            const __half* fh = f + hh * 128;
#pragma unroll
            for (int ch = 0; ch < 4; ch++)
                acc[ch] += a * __half2float(fh[ch * 32 + lane]);
        }
    }
    float* o = out + (size_t)wid * 128;
#pragma unroll
    for (int ch = 0; ch < 4; ch++) o[ch * 32 + lane] = acc[ch];
}

// ---------------- finalize layers 0/1: +bias, LN, +sig*res, ELU + split ----
__global__ void finalize01_kernel(const float* __restrict__ bias,
                                  const float* __restrict__ lng, const float* __restrict__ lnb,
                                  const float* __restrict__ res, const float* __restrict__ rb,
                                  const float* __restrict__ rw, float* __restrict__ out,
                                  __nv_bfloat16* __restrict__ outH,
                                  __nv_bfloat16* __restrict__ outL) {
    int n = blockIdx.x, t = threadIdx.x;   // 256 threads
    float g = g_accb[(size_t)n * 256 + t] + bias[t];
    float s1 = g, s2 = g * g;
#pragma unroll
    for (int o = 16; o; o >>= 1) {
        s1 += __shfl_down_sync(0xffffffffu, s1, o);
        s2 += __shfl_down_sync(0xffffffffu, s2, o);
    }
    __shared__ float sh1[8], sh2[8];
    __shared__ float mu_s, rs_s;
    int w = t >> 5, l = t & 31;
    if (l == 0) { sh1[w] = s1; sh2[w] = s2; }
    __syncthreads();
    if (t == 0) {
        float a = 0.f, b = 0.f;
#pragma unroll
        for (int i = 0; i < 8; i++) { a += sh1[i]; b += sh2[i]; }
        float mu = a * (1.f / 256.f);
        float var = b * (1.f / 256.f) - mu * mu;
        mu_s = mu;
        rs_s = rsqrtf(var + 1e-5f);
    }
    __syncthreads();
    float y = (g - mu_s) * rs_s * lng[t] + lnb[t];
    float sig = 1.f / (1.f + expf(-rw[0]));
    float r = res[(size_t)n * 256 + t];
    if (rb) r += rb[t];
    float z = y + sig * r;
    z = z > 0.f ? z : expm1f(z);   // elu
    size_t o = (size_t)n * 256 + t;
    out[o] = z;
    __nv_bfloat16 zh = __float2bfloat16(z);
    outH[o] = zh;
    outL[o] = __float2bfloat16(z - __bfloat162float(zh));
}

// ---------------- finalize layer 2: +bias, LN, +sig*res (no elu) -----------
__global__ void finalize2_kernel(const float* __restrict__ bias,
                                 const float* __restrict__ lng, const float* __restrict__ lnb,
                                 const float* __restrict__ res, const float* __restrict__ rb,
                                 const float* __restrict__ rw, float* __restrict__ out) {
    int n = blockIdx.x, t = threadIdx.x;   // 128 threads
    float g = g_accb[(size_t)n * 128 + t] + bias[t];
    float s1 = g, s2 = g * g;
#pragma unroll
    for (int o = 16; o; o >>= 1) {
        s1 += __shfl_down_sync(0xffffffffu, s1, o);
        s2 += __shfl_down_sync(0xffffffffu, s2, o);
    }
    __shared__ float sh1[4], sh2[4];
    __shared__ float mu_s, rs_s;
    int w = t >> 5, l = t & 31;
    if (l == 0) { sh1[w] = s1; sh2[w] = s2; }
    __syncthreads();
    if (t == 0) {
        float a = 0.f, b = 0.f;
#pragma unroll
        for (int i = 0; i < 4; i++) { a += sh1[i]; b += sh2[i]; }
        float mu = a * (1.f / 128.f);
        float var = b * (1.f / 128.f) - mu * mu;
        mu_s = mu;
        rs_s = rsqrtf(var + 1e-5f);
    }
    __syncthreads();
    float y = (g - mu_s) * rs_s * lng[t] + lnb[t];
    float sig = 1.f / (1.f + expf(-rw[0]));
    float r = res[(size_t)n * 128 + t] + rb[t];
    out[(size_t)n * 128 + t] = y + sig * r;
}

// ---------------------------------------------------------------------------
extern "C" void kernel_launch(void* const* d_in, const int* in_sizes, int n_in,
                              void* d_out, int out_size) {
    const float* x   = (const float*)d_in[0];
    const void*  ei  = d_in[1];                   // int32 or int64, detected on device
    const float* W0  = (const float*)d_in[2];
    const float* b0  = (const float*)d_in[3];
    const float* as0 = (const float*)d_in[4];
    const float* ad0 = (const float*)d_in[5];
    const float* lng0= (const float*)d_in[6];
    const float* lnb0= (const float*)d_in[7];
    const float* rW0 = (const float*)d_in[8];
    const float* rb0 = (const float*)d_in[9];
    const float* rw0 = (const float*)d_in[10];
    const float* W1  = (const float*)d_in[11];
    const float* b1  = (const float*)d_in[12];
    const float* as1 = (const float*)d_in[13];
    const float* ad1 = (const float*)d_in[14];
    const float* lng1= (const float*)d_in[15];
    const float* lnb1= (const float*)d_in[16];
    const float* rw1 = (const float*)d_in[17];
    const float* W2  = (const float*)d_in[18];
    const float* b2  = (const float*)d_in[19];
    const float* as2 = (const float*)d_in[20];
    const float* ad2 = (const float*)d_in[21];
    const float* lng2= (const float*)d_in[22];
    const float* lnb2= (const float*)d_in[23];
    const float* rW2 = (const float*)d_in[24];
    const float* rb2 = (const float*)d_in[25];
    const float* rw2 = (const float*)d_in[26];

    float *feat, *act0, *act1, *res, *accb;
    __half *feath;
    __nv_bfloat16 *Ah, *Al, *Bh, *Bl;
    cudaGetSymbolAddress((void**)&feat, g_feat);
    cudaGetSymbolAddress((void**)&feath, g_feath);
    cudaGetSymbolAddress((void**)&act0, g_act0);
    cudaGetSymbolAddress((void**)&act1, g_act1);
    cudaGetSymbolAddress((void**)&res,  g_resb);
    cudaGetSymbolAddress((void**)&accb, g_accb);
    cudaGetSymbolAddress((void**)&Ah, g_Ah);
    cudaGetSymbolAddress((void**)&Al, g_Al);
    cudaGetSymbolAddress((void**)&Bh, g_Bh);
    cudaGetSymbolAddress((void**)&Bl, g_Bl);

    const int TB = 256;
    detect_kernel<<<1, 256>>>((const int*)ei);
    pad_kernel<<<((MP - NN) * 256 + TB - 1) / TB, TB>>>();
    build_edges_kernel<<<(ET + TB - 1) / TB, TB>>>(ei);
    csr_partial_kernel<<<NBLK, 256>>>();
    csr_scanb_kernel<<<1, 32>>>();
    csr_offsets_kernel<<<NBLK, 256>>>();
    scatter_kernel<<<(ET + TB - 1) / TB, TB>>>();
    wsplit_kernel<<<(98304 + TB - 1) / TB, TB>>>(W0, rW0, W1, W2, rW2);
    split_kernel<<<(MP * 64 / 4 + TB - 1) / TB, TB>>>(x, Ah, Al, NN * 64, MP * 64);

    int alBlocks  = (NN * 32 + TB - 1) / TB;   // warp per node
    int aggBlocks = (NN * 32 + TB - 1) / TB;
    const int MROWS = MP / 128;   // 157

    // ---------------- layer 0 ----------------
    gemm_tc_kernel<<<dim3(2, MROWS), 256>>>(Ah, Al, Bh, Bl, feat, feath, 256, 64);
    gemm_tc_kernel<<<dim3(2, MROWS), 256>>>(Ah, Al, Bh + 16384, Bl + 16384, res, nullptr, 256, 64);
    al_small_kernel<<<alBlocks, TB>>>(as0, ad0);
    agg_small_kernel<<<aggBlocks, TB>>>(feath, accb);
    finalize01_kernel<<<NN, 256>>>(b0, lng0, lnb0, res, rb0, rw0, act0, Ah, Al);

    // ---------------- layer 1 ----------------
    gemm_tc_kernel<<<dim3(2, MROWS), 256>>>(Ah, Al, Bh + 32768, Bl + 32768, feat, feath, 256, 256);
    al_small_kernel<<<alBlocks, TB>>>(as1, ad1);
    agg_small_kernel<<<aggBlocks, TB>>>(feath, accb);
    finalize01_kernel<<<NN, 256>>>(b1, lng1, lnb1, act0, nullptr, rw1, act1, Ah, Al);

    // ---------------- layer 2 ----------------
    gemm_tc_kernel<<<dim3(8, MROWS), 256>>>(Ah, Al, Bh + 98304, Bl + 98304, feat, feath, 1024, 256);
    gemm_tc_kernel<<<dim3(1, MROWS), 256>>>(Ah, Al, Bh + 360448, Bl + 360448, res, nullptr, 128, 256);
    al_big_kernel<<<alBlocks, TB>>>(as2, ad2);
    agg_big_kernel<<<aggBlocks, TB>>>(feath, accb);
    finalize2_kernel<<<NN, 128>>>(b2, lng2, lnb2, res, rb2, rw2, (float*)d_out);
}

// round 14
// speedup vs baseline: 1.7817x; 1.0669x over previous
#include <cuda_runtime.h>
#include <cuda_bf16.h>
#include <cuda_fp16.h>
#include <cstdint>
#include <mma.h>
using namespace nvcuda;

// Problem constants (fixed by the reference)
#define NN 20000
#define EE 320000
#define ET (NN + EE)          // edges incl. self loops = 340000
#define HEADS 8
#define MP 20096              // NN padded to multiple of 128 for tensor GEMM
#define NBLK ((NN + 255) / 256)   // 79 blocks for CSR scan

// ---------------- scratch (device globals: no allocation allowed) ----------
__device__ float g_feat[(size_t)MP * 1152];   // transformed features (+res cols)
__device__ __half g_feath[(size_t)MP * 1024]; // fp16 shadow for gathers
__device__ float g_accb[(size_t)NN * 256];    // aggregation output
__device__ float g_act0[(size_t)NN * 256];    // activation after layer 0
__device__ float g_act1[(size_t)NN * 256];    // activation after layer 1
__device__ float g_als[NN * HEADS];
__device__ float g_ald[NN * HEADS];
__device__ int g_src[ET];
__device__ int g_dst[ET];
__device__ int g_is64;
// CSR (dst-sorted adjacency)
__device__ int g_deg[NN];
__device__ int g_off[NN + 1];
__device__ int g_cur[NN];
__device__ int g_csr_src[ET];
__device__ int g_bsum[NBLK];
__device__ int g_boff[NBLK];

// bf16 split buffers. A: activations (MP x 256 max). B: ALL weights, segmented:
//   [W0|rW0] concat [64,512] @ 0 (32768 elems)
//   W1 [256,256] @ 32768 (65536)
//   [W2|rW2] concat [256,1152] @ 98304 (294912)  -> total 393216
__device__ __nv_bfloat16 g_Ah[(size_t)MP * 256];
__device__ __nv_bfloat16 g_Al[(size_t)MP * 256];
__device__ __nv_bfloat16 g_Bh[393216];
__device__ __nv_bfloat16 g_Bl[393216];

// ---------------- dtype detection: int64 vs int32 edge_index ---------------
__global__ void detect_kernel(const int* __restrict__ raw) {
    __shared__ int any;
    if (threadIdx.x == 0) any = 0;
    __syncthreads();
    for (int i = threadIdx.x; i < 2048; i += blockDim.x)
        if (raw[2 * i + 1] != 0) any = 1;
    __syncthreads();
    if (threadIdx.x == 0) g_is64 = (any == 0);
}

// ---------------- pad: zero A padding rows + degree array ------------------
__global__ void pad_kernel() {
    int i = blockIdx.x * blockDim.x + threadIdx.x;
    if (i < NN) g_deg[i] = 0;
    int tot = (MP - NN) * 256;
    if (i < tot) {
        g_Ah[(size_t)NN * 256 + i] = __float2bfloat16(0.f);
        g_Al[(size_t)NN * 256 + i] = __float2bfloat16(0.f);
    }
}

// ---------------- edge list build (+self loops) + degree histogram ---------
__global__ void build_edges_kernel(const void* __restrict__ eiraw) {
    int i = blockIdx.x * blockDim.x + threadIdx.x;
    if (i >= ET) return;
    int s, d;
    if (i < EE) {
        if (g_is64) {
            const long long* e = (const long long*)eiraw;
            s = (int)e[i];
            d = (int)e[EE + i];
        } else {
            const int* e = (const int*)eiraw;
            s = e[i];
            d = e[EE + i];
        }
        s = min(max(s, 0), NN - 1);
        d = min(max(d, 0), NN - 1);
    } else {
        s = d = i - EE;   // self loop
    }
    g_src[i] = s;
    g_dst[i] = d;
    atomicAdd(&g_deg[d], 1);
}

// ---------------- CSR: 3-phase parallel scan + scatter ---------------------
__global__ void csr_partial_kernel() {
    __shared__ int sh[256];
    int idx = blockIdx.x * 256 + threadIdx.x;
    int v = (idx < NN) ? g_deg[idx] : 0;
    sh[threadIdx.x] = v;
    __syncthreads();
    for (int off = 128; off; off >>= 1) {
        if (threadIdx.x < off) sh[threadIdx.x] += sh[threadIdx.x + off];
        __syncthreads();
    }
    if (threadIdx.x == 0) g_bsum[blockIdx.x] = sh[0];
}

__global__ void csr_scanb_kernel() {
    if (threadIdx.x == 0) {
        int run = 0;
        for (int i = 0; i < NBLK; i++) { g_boff[i] = run; run += g_bsum[i]; }
        g_off[NN] = ET;
    }
}

__global__ void csr_offsets_kernel() {
    __shared__ int sh[256];
    int idx = blockIdx.x * 256 + threadIdx.x;
    int v = (idx < NN) ? g_deg[idx] : 0;
    sh[threadIdx.x] = v;
    __syncthreads();
    for (int off = 1; off < 256; off <<= 1) {
        int u = (threadIdx.x >= off) ? sh[threadIdx.x - off] : 0;
        __syncthreads();
        sh[threadIdx.x] += u;
        __syncthreads();
    }
    if (idx < NN) {
        int excl = g_boff[blockIdx.x] + sh[threadIdx.x] - v;
        g_off[idx] = excl;
        g_cur[idx] = excl;
    }
}

__global__ void scatter_kernel() {
    int i = blockIdx.x * blockDim.x + threadIdx.x;
    if (i >= ET) return;
    int d = g_dst[i];
    int pos = atomicAdd(&g_cur[d], 1);
    g_csr_src[pos] = g_src[i];
}

// ---------------- fp32 -> bf16 hi/lo split (x-features, vectorized) --------
__global__ void split_kernel(const float* __restrict__ X,
                             __nv_bfloat16* __restrict__ H,
                             __nv_bfloat16* __restrict__ L,
                             int realElems, int totElems) {
    int i = (blockIdx.x * blockDim.x + threadIdx.x) * 4;
    if (i >= totElems) return;
    float4 v = (i < realElems) ? *(const float4*)&X[i] : make_float4(0.f, 0.f, 0.f, 0.f);
    __nv_bfloat162 h01 = {__float2bfloat16(v.x), __float2bfloat16(v.y)};
    __nv_bfloat162 h23 = {__float2bfloat16(v.z), __float2bfloat16(v.w)};
    __nv_bfloat162 l01 = {__float2bfloat16(v.x - __bfloat162float(h01.x)),
                          __float2bfloat16(v.y - __bfloat162float(h01.y))};
    __nv_bfloat162 l23 = {__float2bfloat16(v.z - __bfloat162float(h23.x)),
                          __float2bfloat16(v.w - __bfloat162float(h23.y))};
    *(__nv_bfloat162*)&H[i] = h01;
    *(__nv_bfloat162*)&H[i + 2] = h23;
    *(__nv_bfloat162*)&L[i] = l01;
    *(__nv_bfloat162*)&L[i + 2] = l23;
}

// ---------------- ALL weight matrices split + concat layouts ---------------
// Region 0: [W0|rW0] -> [64,512]   elems 0..32767
// Region 1: W1        -> [256,256] elems 32768..98303
// Region 2: [W2|rW2] -> [256,1152] elems 98304..393215
__global__ void wsplit_kernel(const float* __restrict__ W0, const float* __restrict__ rW0,
                              const float* __restrict__ W1, const float* __restrict__ W2,
                              const float* __restrict__ rW2) {
    int i4 = blockIdx.x * blockDim.x + threadIdx.x;    // float4 index, total 98304
    if (i4 >= 98304) return;
    const float4* src4; size_t dstElem;
    if (i4 < 8192) {                       // layer0 concat: 128 f4 per row
        int k = i4 >> 7, j = i4 & 127;
        if (j < 64) { src4 = (const float4*)W0 + (k * 64 + j);  dstElem = (size_t)k * 512 + j * 4; }
        else        { src4 = (const float4*)rW0 + (k * 64 + j - 64); dstElem = (size_t)k * 512 + 256 + (j - 64) * 4; }
    } else if (i4 < 24576) {               // W1 linear
        int e4 = i4 - 8192;
        src4 = (const float4*)W1 + e4;
        dstElem = 32768 + (size_t)e4 * 4;
    } else {                               // layer2 concat: 288 f4 per row
        int e4 = i4 - 24576;
        int k = e4 / 288, j = e4 - k * 288;
        if (j < 256) { src4 = (const float4*)W2 + (k * 256 + j); dstElem = 98304 + (size_t)k * 1152 + j * 4; }
        else         { src4 = (const float4*)rW2 + (k * 32 + j - 256); dstElem = 98304 + (size_t)k * 1152 + 1024 + (j - 256) * 4; }
    }
    float4 v = *src4;
    __nv_bfloat162 h01 = {__float2bfloat16(v.x), __float2bfloat16(v.y)};
    __nv_bfloat162 h23 = {__float2bfloat16(v.z), __float2bfloat16(v.w)};
    __nv_bfloat162 l01 = {__float2bfloat16(v.x - __bfloat162float(h01.x)),
                          __float2bfloat16(v.y - __bfloat162float(h01.y))};
    __nv_bfloat162 l23 = {__float2bfloat16(v.z - __bfloat162float(h23.x)),
                          __float2bfloat16(v.w - __bfloat162float(h23.y))};
    *(__nv_bfloat162*)&g_Bh[dstElem] = h01;
    *(__nv_bfloat162*)&g_Bh[dstElem + 2] = h23;
    *(__nv_bfloat162*)&g_Bl[dstElem] = l01;
    *(__nv_bfloat162*)&g_Bl[dstElem + 2] = l23;
}

// ---------------- tensor-core GEMM (static smem + register prefetch) -------
// C[MP,N] = A @ B, split-bf16 3-product. Block 128x128, BK=32, 8 warps.
// Next k-tile loaded into registers during compute (no extra smem -> keeps occupancy).
// fp16 shadow (stride S) written in epilogue for blocks with col0 < S.
struct __align__(256) SmemA { __nv_bfloat16 d[128][40]; };
struct __align__(256) SmemB { __nv_bfloat16 d[32][136]; };

__global__ void __launch_bounds__(256) gemm_tc_kernel(
    const __nv_bfloat16* __restrict__ Ah, const __nv_bfloat16* __restrict__ Al,
    const __nv_bfloat16* __restrict__ Bh, const __nv_bfloat16* __restrict__ Bl,
    float* __restrict__ C, __half* __restrict__ Cf16, int N, int K, int S)
{
    __shared__ SmemA sAh, sAl;
    __shared__ SmemB sBh, sBl;
    int tid = threadIdx.x;
    int warp = tid >> 5;
    int wm = warp & 1, wn = warp >> 1;           // 2 x 4 warp grid
    int row0 = blockIdx.y * 128, col0 = blockIdx.x * 128;

    wmma::fragment<wmma::accumulator, 16, 16, 16, float> acc[4][2];
#pragma unroll
    for (int i = 0; i < 4; i++)
#pragma unroll
        for (int j = 0; j < 2; j++) wmma::fill_fragment(acc[i][j], 0.f);

    const int nk = K >> 5;
    uint4 rA[4], rB[4];

    auto loadRegs = [&](int k0) {
#pragma unroll
        for (int u = 0; u < 2; u++) {
            int v = tid + u * 256;
            int r = v >> 2, kk = (v & 3) * 8;
            size_t g = (size_t)(row0 + r) * K + k0 + kk;
            rA[u * 2]     = *(const uint4*)&Ah[g];
            rA[u * 2 + 1] = *(const uint4*)&Al[g];
        }
#pragma unroll
        for (int u = 0; u < 2; u++) {
            int v = tid + u * 256;
            int r = v >> 4, cc = (v & 15) * 8;
            size_t g = (size_t)(k0 + r) * N + col0 + cc;
            rB[u * 2]     = *(const uint4*)&Bh[g];
            rB[u * 2 + 1] = *(const uint4*)&Bl[g];
        }
    };
    auto storeRegs = [&]() {
#pragma unroll
        for (int u = 0; u < 2; u++) {
            int v = tid + u * 256;
            int r = v >> 2, kk = (v & 3) * 8;
            *(uint4*)&sAh.d[r][kk] = rA[u * 2];
            *(uint4*)&sAl.d[r][kk] = rA[u * 2 + 1];
        }
#pragma unroll
        for (int u = 0; u < 2; u++) {
            int v = tid + u * 256;
            int r = v >> 4, cc = (v & 15) * 8;
            *(uint4*)&sBh.d[r][cc] = rB[u * 2];
            *(uint4*)&sBl.d[r][cc] = rB[u * 2 + 1];
        }
    };

    loadRegs(0);
    for (int it = 0; it < nk; it++) {
        storeRegs();
        __syncthreads();
        if (it + 1 < nk) loadRegs((it + 1) * 32);   // overlap with compute below
#pragma unroll
        for (int ks = 0; ks < 32; ks += 16) {
            wmma::fragment<wmma::matrix_a, 16, 16, 16, __nv_bfloat16, wmma::row_major> fah[4], fal[4];
            wmma::fragment<wmma::matrix_b, 16, 16, 16, __nv_bfloat16, wmma::row_major> fbh[2], fbl[2];
#pragma unroll
            for (int i = 0; i < 4; i++) {
                wmma::load_matrix_sync(fah[i], &sAh.d[wm * 64 + i * 16][ks], 40);
                wmma::load_matrix_sync(fal[i], &sAl.d[wm * 64 + i * 16][ks], 40);
            }
#pragma unroll
            for (int j = 0; j < 2; j++) {
                wmma::load_matrix_sync(fbh[j], &sBh.d[ks][wn * 32 + j * 16], 136);
                wmma::load_matrix_sync(fbl[j], &sBl.d[ks][wn * 32 + j * 16], 136);
            }
#pragma unroll
            for (int i = 0; i < 4; i++)
#pragma unroll
                for (int j = 0; j < 2; j++) {
                    wmma::mma_sync(acc[i][j], fah[i], fbh[j], acc[i][j]);
                    wmma::mma_sync(acc[i][j], fal[i], fbh[j], acc[i][j]);
                    wmma::mma_sync(acc[i][j], fah[i], fbl[j], acc[i][j]);
                }
        }
        __syncthreads();
    }
#pragma unroll
    for (int i = 0; i < 4; i++)
#pragma unroll
        for (int j = 0; j < 2; j++)
            wmma::store_matrix_sync(&C[(size_t)(row0 + wm * 64 + i * 16) * N +
                                       col0 + wn * 32 + j * 16],
                                    acc[i][j], N, wmma::mem_row_major);

    if (Cf16 && col0 < S) {
        __syncthreads();   // other warps' C stores visible (same SM/L1)
        for (int idx = tid; idx < 4096; idx += 256) {
            int r = idx >> 5, cch = idx & 31;
            size_t gs = (size_t)(row0 + r) * N + col0 + cch * 4;
            float4 v = *(const float4*)&C[gs];
            __half2 a = __floats2half2_rn(v.x, v.y);
            __half2 b = __floats2half2_rn(v.z, v.w);
            size_t gd = (size_t)(row0 + r) * S + col0 + cch * 4;
            *(__half2*)&Cf16[gd] = a;
            *(__half2*)&Cf16[gd + 2] = b;
        }
    }
}

// ---------------- attention logits, warp per node (coalesced) --------------
__global__ void al_small_kernel(const float* __restrict__ a_s, const float* __restrict__ a_d,
                                int stride) {
    int node = (blockIdx.x * blockDim.x + threadIdx.x) >> 5;
    if (node >= NN) return;
    int lane = threadIdx.x & 31;
    const float4* f = (const float4*)(g_feat + (size_t)node * stride) + lane * 2;
    const float4* ws = (const float4*)a_s + lane * 2;
    const float4* wd = (const float4*)a_d + lane * 2;
    float4 v0 = f[0], v1 = f[1];
    float4 w0 = ws[0], w1 = ws[1];
    float4 u0 = wd[0], u1 = wd[1];
    float s1 = v0.x * w0.x + v0.y * w0.y + v0.z * w0.z + v0.w * w0.w
             + v1.x * w1.x + v1.y * w1.y + v1.z * w1.z + v1.w * w1.w;
    float s2 = v0.x * u0.x + v0.y * u0.y + v0.z * u0.z + v0.w * u0.w
             + v1.x * u1.x + v1.y * u1.y + v1.z * u1.z + v1.w * u1.w;
    s1 += __shfl_xor_sync(0xffffffffu, s1, 1);
    s1 += __shfl_xor_sync(0xffffffffu, s1, 2);
    s2 += __shfl_xor_sync(0xffffffffu, s2, 1);
    s2 += __shfl_xor_sync(0xffffffffu, s2, 2);
    if ((lane & 3) == 0) {
        int h = lane >> 2;
        g_als[node * 8 + h] = s1;
        g_ald[node * 8 + h] = s2;
    }
}

__global__ void al_big_kernel(const float* __restrict__ a_s, const float* __restrict__ a_d,
                              int stride) {
    int node = (blockIdx.x * blockDim.x + threadIdx.x) >> 5;
    if (node >= NN) return;
    int lane = threadIdx.x & 31;
    const float4* f = (const float4*)(g_feat + (size_t)node * stride) + lane * 8;
    const float4* ws = (const float4*)a_s + lane * 8;
    const float4* wd = (const float4*)a_d + lane * 8;
    float s1 = 0.f, s2 = 0.f;
#pragma unroll
    for (int j = 0; j < 8; j++) {
        float4 v = f[j], w = ws[j], u = wd[j];
        s1 += v.x * w.x + v.y * w.y + v.z * w.z + v.w * w.w;
        s2 += v.x * u.x + v.y * u.y + v.z * u.z + v.w * u.w;
    }
    s1 += __shfl_xor_sync(0xffffffffu, s1, 1);
    s1 += __shfl_xor_sync(0xffffffffu, s1, 2);
    s2 += __shfl_xor_sync(0xffffffffu, s2, 1);
    s2 += __shfl_xor_sync(0xffffffffu, s2, 2);
    if ((lane & 3) == 0) {
        int h = lane >> 2;
        g_als[node * 8 + h] = s1;
        g_ald[node * 8 + h] = s2;
    }
}

// ---------------- fused aggregation (layers 0/1, C=32), warp per dst -------
__global__ void __launch_bounds__(256) agg_small_kernel(const __half* __restrict__ feath,
                                                        float* __restrict__ out) {
    int wid = (blockIdx.x * blockDim.x + threadIdx.x) >> 5;
    if (wid >= NN) return;
    int lane = threadIdx.x & 31;
    int h = lane & 7;
    int beg = g_off[wid], end = g_off[wid + 1];
    float ald_h = g_ald[wid * HEADS + h];

    float m = -1e30f;
    for (int i = beg + (lane >> 3); i < end; i += 4) {
        int s = g_csr_src[i];
        float ev = g_als[s * HEADS + h] + ald_h;
        ev = ev > 0.f ? ev : 0.2f * ev;
        m = fmaxf(m, ev);
    }
    m = fmaxf(m, __shfl_xor_sync(0xffffffffu, m, 8));
    m = fmaxf(m, __shfl_xor_sync(0xffffffffu, m, 16));
    float ssum = 0.f;
    for (int i = beg + (lane >> 3); i < end; i += 4) {
        int s = g_csr_src[i];
        float ev = g_als[s * HEADS + h] + ald_h;
        ev = ev > 0.f ? ev : 0.2f * ev;
        ssum += expf(ev - m);
    }
    ssum += __shfl_xor_sync(0xffffffffu, ssum, 8);
    ssum += __shfl_xor_sync(0xffffffffu, ssum, 16);
    float inv = 1.f / (ssum + 1e-16f);

    float acc[8] = {0.f, 0.f, 0.f, 0.f, 0.f, 0.f, 0.f, 0.f};
    for (int i = beg; i < end; i++) {
        int s = g_csr_src[i];
        float ev = g_als[s * HEADS + h] + ald_h;
        ev = ev > 0.f ? ev : 0.2f * ev;
        float alpha = expf(ev - m) * inv;
        const __half* f = feath + (size_t)s * 256;
#pragma unroll
        for (int hh = 0; hh < 8; hh++) {
            float a = __shfl_sync(0xffffffffu, alpha, hh);
            acc[hh] += a * __half2float(f[hh * 32 + lane]);
        }
    }
    float* o = out + (size_t)wid * 256;
#pragma unroll
    for (int hh = 0; hh < 8; hh++) o[hh * 32 + lane] = acc[hh];
}

// ---------------- fused aggregation (layer 2, C=128, mean over heads) ------
__global__ void __launch_bounds__(256) agg_big_kernel(const __half* __restrict__ feath,
                                                      float* __restrict__ out) {
    int wid = (blockIdx.x * blockDim.x + threadIdx.x) >> 5;
    if (wid >= NN) return;
    int lane = threadIdx.x & 31;
    int h = lane & 7;
    int beg = g_off[wid], end = g_off[wid + 1];
    float ald_h = g_ald[wid * HEADS + h];

    float m = -1e30f;
    for (int i = beg + (lane >> 3); i < end; i += 4) {
        int s = g_csr_src[i];
        float ev = g_als[s * HEADS + h] + ald_h;
        ev = ev > 0.f ? ev : 0.2f * ev;
        m = fmaxf(m, ev);
    }
    m = fmaxf(m, __shfl_xor_sync(0xffffffffu, m, 8));
    m = fmaxf(m, __shfl_xor_sync(0xffffffffu, m, 16));
    float ssum = 0.f;
    for (int i = beg + (lane >> 3); i < end; i += 4) {
        int s = g_csr_src[i];
        float ev = g_als[s * HEADS + h] + ald_h;
        ev = ev > 0.f ? ev : 0.2f * ev;
        ssum += expf(ev - m);
    }
    ssum += __shfl_xor_sync(0xffffffffu, ssum, 8);
    ssum += __shfl_xor_sync(0xffffffffu, ssum, 16);
    float inv = 0.125f / (ssum + 1e-16f);

    float acc[4] = {0.f, 0.f, 0.f, 0.f};
    for (int i = beg; i < end; i++) {
        int s = g_csr_src[i];
        float ev = g_als[s * HEADS + h] + ald_h;
        ev = ev > 0.f ? ev : 0.2f * ev;
        float alpha = expf(ev - m) * inv;
        const __half* f = feath + (size_t)s * 1024;
#pragma unroll
        for (int hh = 0; hh < 8; hh++) {
            float a = __shfl_sync(0xffffffffu, alpha, hh);
            const __half* fh = f + hh * 128;
#pragma unroll
            for (int ch = 0; ch < 4; ch++)
                acc[ch] += a * __half2float(fh[ch * 32 + lane]);
        }
    }
    float* o = out + (size_t)wid * 128;
#pragma unroll
    for (int ch = 0; ch < 4; ch++) o[ch * 32 + lane] = acc[ch];
}

// ---------------- finalize layers 0/1: +bias, LN, +sig*res, ELU + split ----
__global__ void finalize01_kernel(const float* __restrict__ bias,
                                  const float* __restrict__ lng, const float* __restrict__ lnb,
                                  const float* __restrict__ res, int resStride,
                                  const float* __restrict__ rb,
                                  const float* __restrict__ rw, float* __restrict__ out,
                                  __nv_bfloat16* __restrict__ outH,
                                  __nv_bfloat16* __restrict__ outL) {
    int n = blockIdx.x, t = threadIdx.x;   // 256 threads
    float g = g_accb[(size_t)n * 256 + t] + bias[t];
    float s1 = g, s2 = g * g;
#pragma unroll
    for (int o = 16; o; o >>= 1) {
        s1 += __shfl_down_sync(0xffffffffu, s1, o);
        s2 += __shfl_down_sync(0xffffffffu, s2, o);
    }
    __shared__ float sh1[8], sh2[8];
    __shared__ float mu_s, rs_s;
    int w = t >> 5, l = t & 31;
    if (l == 0) { sh1[w] = s1; sh2[w] = s2; }
    __syncthreads();
    if (t == 0) {
        float a = 0.f, b = 0.f;
#pragma unroll
        for (int i = 0; i < 8; i++) { a += sh1[i]; b += sh2[i]; }
        float mu = a * (1.f / 256.f);
        float var = b * (1.f / 256.f) - mu * mu;
        mu_s = mu;
        rs_s = rsqrtf(var + 1e-5f);
    }
    __syncthreads();
    float y = (g - mu_s) * rs_s * lng[t] + lnb[t];
    float sig = 1.f / (1.f + expf(-rw[0]));
    float r = res[(size_t)n * resStride + t];
    if (rb) r += rb[t];
    float z = y + sig * r;
    z = z > 0.f ? z : expm1f(z);   // elu
    size_t o = (size_t)n * 256 + t;
    out[o] = z;
    __nv_bfloat16 zh = __float2bfloat16(z);
    outH[o] = zh;
    outL[o] = __float2bfloat16(z - __bfloat162float(zh));
}

// ---------------- finalize layer 2: +bias, LN, +sig*res (no elu) -----------
__global__ void finalize2_kernel(const float* __restrict__ bias,
                                 const float* __restrict__ lng, const float* __restrict__ lnb,
                                 const float* __restrict__ res, int resStride,
                                 const float* __restrict__ rb,
                                 const float* __restrict__ rw, float* __restrict__ out) {
    int n = blockIdx.x, t = threadIdx.x;   // 128 threads
    float g = g_accb[(size_t)n * 128 + t] + bias[t];
    float s1 = g, s2 = g * g;
#pragma unroll
    for (int o = 16; o; o >>= 1) {
        s1 += __shfl_down_sync(0xffffffffu, s1, o);
        s2 += __shfl_down_sync(0xffffffffu, s2, o);
    }
    __shared__ float sh1[4], sh2[4];
    __shared__ float mu_s, rs_s;
    int w = t >> 5, l = t & 31;
    if (l == 0) { sh1[w] = s1; sh2[w] = s2; }
    __syncthreads();
    if (t == 0) {
        float a = 0.f, b = 0.f;
#pragma unroll
        for (int i = 0; i < 4; i++) { a += sh1[i]; b += sh2[i]; }
        float mu = a * (1.f / 128.f);
        float var = b * (1.f / 128.f) - mu * mu;
        mu_s = mu;
        rs_s = rsqrtf(var + 1e-5f);
    }
    __syncthreads();
    float y = (g - mu_s) * rs_s * lng[t] + lnb[t];
    float sig = 1.f / (1.f + expf(-rw[0]));
    float r = res[(size_t)n * resStride + t] + rb[t];
    out[(size_t)n * 128 + t] = y + sig * r;
}

// ---------------------------------------------------------------------------
extern "C" void kernel_launch(void* const* d_in, const int* in_sizes, int n_in,
                              void* d_out, int out_size) {
    const float* x   = (const float*)d_in[0];
    const void*  ei  = d_in[1];                   // int32 or int64, detected on device
    const float* W0  = (const float*)d_in[2];
    const float* b0  = (const float*)d_in[3];
    const float* as0 = (const float*)d_in[4];
    const float* ad0 = (const float*)d_in[5];
    const float* lng0= (const float*)d_in[6];
    const float* lnb0= (const float*)d_in[7];
    const float* rW0 = (const float*)d_in[8];
    const float* rb0 = (const float*)d_in[9];
    const float* rw0 = (const float*)d_in[10];
    const float* W1  = (const float*)d_in[11];
    const float* b1  = (const float*)d_in[12];
    const float* as1 = (const float*)d_in[13];
    const float* ad1 = (const float*)d_in[14];
    const float* lng1= (const float*)d_in[15];
    const float* lnb1= (const float*)d_in[16];
    const float* rw1 = (const float*)d_in[17];
    const float* W2  = (const float*)d_in[18];
    const float* b2  = (const float*)d_in[19];
    const float* as2 = (const float*)d_in[20];
    const float* ad2 = (const float*)d_in[21];
    const float* lng2= (const float*)d_in[22];
    const float* lnb2= (const float*)d_in[23];
    const float* rW2 = (const float*)d_in[24];
    const float* rb2 = (const float*)d_in[25];
    const float* rw2 = (const float*)d_in[26];

    float *feat, *act0, *act1, *accb;
    __half *feath;
    __nv_bfloat16 *Ah, *Al, *Bh, *Bl;
    cudaGetSymbolAddress((void**)&feat, g_feat);
    cudaGetSymbolAddress((void**)&feath, g_feath);
    cudaGetSymbolAddress((void**)&act0, g_act0);
    cudaGetSymbolAddress((void**)&act1, g_act1);
    cudaGetSymbolAddress((void**)&accb, g_accb);
    cudaGetSymbolAddress((void**)&Ah, g_Ah);
    cudaGetSymbolAddress((void**)&Al, g_Al);
    cudaGetSymbolAddress((void**)&Bh, g_Bh);
    cudaGetSymbolAddress((void**)&Bl, g_Bl);

    const int TB = 256;
    detect_kernel<<<1, 256>>>((const int*)ei);
    pad_kernel<<<((MP - NN) * 256 + TB - 1) / TB, TB>>>();
    build_edges_kernel<<<(ET + TB - 1) / TB, TB>>>(ei);
    wsplit_kernel<<<(98304 + TB - 1) / TB, TB>>>(W0, rW0, W1, W2, rW2);
    split_kernel<<<(MP * 64 / 4 + TB - 1) / TB, TB>>>(x, Ah, Al, NN * 64, MP * 64);

    int alBlocks  = (NN * 32 + TB - 1) / TB;   // warp per node
    int aggBlocks = (NN * 32 + TB - 1) / TB;
    const int MROWS = MP / 128;   // 157

    // ---------------- layer 0 (GEMM first so ncu profiles it) --------------
    gemm_tc_kernel<<<dim3(4, MROWS), 256>>>(Ah, Al, Bh, Bl, feat, feath, 512, 64, 256);
    // CSR build (independent of GEMM; needed before agg)
    csr_partial_kernel<<<NBLK, 256>>>();
    csr_scanb_kernel<<<1, 32>>>();
    csr_offsets_kernel<<<NBLK, 256>>>();
    scatter_kernel<<<(ET + TB - 1) / TB, TB>>>();
    al_small_kernel<<<alBlocks, TB>>>(as0, ad0, 512);
    agg_small_kernel<<<aggBlocks, TB>>>(feath, accb);
    finalize01_kernel<<<NN, 256>>>(b0, lng0, lnb0, feat + 256, 512, rb0, rw0, act0, Ah, Al);

    // ---------------- layer 1 ----------------
    gemm_tc_kernel<<<dim3(2, MROWS), 256>>>(Ah, Al, Bh + 32768, Bl + 32768, feat, feath, 256, 256, 256);
    al_small_kernel<<<alBlocks, TB>>>(as1, ad1, 256);
    agg_small_kernel<<<aggBlocks, TB>>>(feath, accb);
    finalize01_kernel<<<NN, 256>>>(b1, lng1, lnb1, act0, 256, nullptr, rw1, act1, Ah, Al);

    // ---------------- layer 2 ----------------
    gemm_tc_kernel<<<dim3(9, MROWS), 256>>>(Ah, Al, Bh + 98304, Bl + 98304, feat, feath, 1152, 256, 1024);
    al_big_kernel<<<alBlocks, TB>>>(as2, ad2, 1152);
    agg_big_kernel<<<aggBlocks, TB>>>(feath, accb);
    finalize2_kernel<<<NN, 128>>>(b2, lng2, lnb2, feat + 1024, 1152, rb2, rw2, (float*)d_out);
}